// round 2
// baseline (speedup 1.0000x reference)
#include <cuda_runtime.h>
#include <math.h>

#define F_DIM 128
#define NPG   100
#define KNUM  80
#define EPG   1600
#define TPB   256

__global__ __launch_bounds__(TPB) void sagpool_fused_kernel(
    const float* __restrict__ x,
    const int*   __restrict__ ei,      // [2, E] row-major: [0..E) = src, [E..2E) = dst
    const float* __restrict__ theta,   // [F]
    float* __restrict__ out,
    int E, int B)
{
    __shared__ __align__(16) float th[F_DIM];
    __shared__ float s[NPG];
    __shared__ float z[NPG];
    __shared__ float dis[NPG];
    __shared__ int   deg[NPG];
    __shared__ int   srcl[EPG];
    __shared__ int   dstl[EPG];
    __shared__ int   kept[NPG];
    __shared__ int   nid[NPG];
    __shared__ int   inv[KNUM];
    __shared__ float scl[KNUM];

    const int b     = blockIdx.x;
    const int t     = threadIdx.x;
    const int base  = b * NPG;
    const int ebase = b * EPG;

    if (t < F_DIM) th[t] = theta[t];
    if (t < NPG)   deg[t] = 1;           // self loop
    __syncthreads();

    // s[i] = dot(x[base+i,:], theta) — one warp per node
    const int warp = t >> 5, lane = t & 31;
    for (int i = warp; i < NPG; i += TPB / 32) {
        const float4* xr = reinterpret_cast<const float4*>(x + (size_t)(base + i) * F_DIM);
        float4 v  = xr[lane];
        float4 tv = reinterpret_cast<const float4*>(th)[lane];
        float d = v.x * tv.x + v.y * tv.y + v.z * tv.z + v.w * tv.w;
        #pragma unroll
        for (int o = 16; o > 0; o >>= 1) d += __shfl_down_sync(0xffffffffu, d, o);
        if (lane == 0) s[i] = d;
    }

    // degree histogram (over src / "row", matching reference) + cache local edges
    for (int e = t; e < EPG; e += TPB) {
        int sg = ei[ebase + e];
        int dg = ei[(size_t)E + ebase + e];
        int sl = sg - base, dl = dg - base;
        srcl[e] = sl; dstl[e] = dl;
        atomicAdd(&deg[sl], 1);
    }
    __syncthreads();

    if (t < NPG) {
        float dd = (float)deg[t];
        dis[t] = rsqrtf(dd);
        z[t]   = s[t] / dd;              // self-loop contribution: dis[i]^2 * s[i]
    }
    __syncthreads();

    // z[dst] += dis[src]*dis[dst]*s[src]
    for (int e = t; e < EPG; e += TPB) {
        int sl = srcl[e], dl = dstl[e];
        atomicAdd(&z[dl], dis[sl] * dis[dl] * s[sl]);
    }
    __syncthreads();

    // top-k by rank counting (matches lax.top_k tie-break: smaller index wins ties)
    if (t < NPG) {
        float zi = z[t];
        int r = 0;
        #pragma unroll 4
        for (int j = 0; j < NPG; j++) {
            float zj = z[j];
            r += (zj > zi) || (zj == zi && j < t);
        }
        kept[t] = (r < KNUM) ? 1 : 0;
    }
    __syncthreads();

    if (t < NPG && kept[t]) {
        int n = 0;
        for (int j = 0; j < t; j++) n += kept[j];
        nid[t]  = n;
        inv[n]  = t;
        scl[n]  = 1.0f / (1.0f + __expf(-z[t]));
    }
    __syncthreads();

    // ---- outputs: [x_new (B*KNUM*F) | edge0 (E) | edge1 (E) | batch (B*KNUM)] ----
    const size_t EOUT0 = (size_t)B * KNUM * F_DIM;
    const size_t EOUT1 = EOUT0 + (size_t)E;
    const size_t BOUT  = EOUT0 + 2 * (size_t)E;

    // x_new = x[keep] * sigmoid(z[keep])   (rows in ascending local-index order)
    for (int tt = t; tt < KNUM * F_DIM; tt += TPB) {
        int r = tt >> 7, f = tt & (F_DIM - 1);
        int i = inv[r];
        float v = x[(size_t)(base + i) * F_DIM + f];
        out[(size_t)(b * KNUM + r) * F_DIM + f] = v * scl[r];
    }

    if (t < KNUM) out[BOUT + (size_t)b * KNUM + t] = (float)b;

    // relabeled edges; -1 if either endpoint dropped
    for (int e = t; e < EPG; e += TPB) {
        int sl = srcl[e], dl = dstl[e];
        float o0 = -1.0f, o1 = -1.0f;
        if (kept[sl] && kept[dl]) {
            o0 = (float)(b * KNUM + nid[sl]);
            o1 = (float)(b * KNUM + nid[dl]);
        }
        out[EOUT0 + ebase + e] = o0;
        out[EOUT1 + ebase + e] = o1;
    }
}

extern "C" void kernel_launch(void* const* d_in, const int* in_sizes, int n_in,
                              void* d_out, int out_size)
{
    const float* x     = (const float*)d_in[0];
    const int*   ei    = (const int*)d_in[1];
    // d_in[2] = batch (unused: graphs are contiguous, batch[i] = i / NPG)
    const float* theta = (const float*)d_in[3];
    float* out = (float*)d_out;

    int N = in_sizes[0] / F_DIM;       // 100000
    int E = in_sizes[1] / 2;           // 1600000
    int B = N / NPG;                   // 1000

    sagpool_fused_kernel<<<B, TPB>>>(x, ei, theta, out, E, B);
}

// round 3
// speedup vs baseline: 1.2260x; 1.2260x over previous
#include <cuda_runtime.h>
#include <math.h>

#define F_DIM 128
#define NPG   100
#define KNUM  80
#define EPG   1600
#define TPB   256
#define NWARP (TPB / 32)

__global__ __launch_bounds__(TPB) void sagpool_fused_kernel(
    const float* __restrict__ x,
    const int*   __restrict__ ei,      // [2, E]: [0..E) = src, [E..2E) = dst
    const float* __restrict__ theta,   // [F]
    float* __restrict__ out,
    int E, int B)
{
    __shared__ __align__(16) float th[F_DIM];
    __shared__ float s[NPG];           // dot(x_i, theta); later s_i/deg_i (self term)
    __shared__ float us[NPG];          // dis_i * s_i
    __shared__ float z[NPG];           // scatter accumulator, then final score
    __shared__ float dis[NPG];
    __shared__ int   degp[NWARP][NPG]; // per-warp private degree histograms
    __shared__ __align__(16) int srcl[EPG];
    __shared__ __align__(16) int dstl[EPG];
    __shared__ int   kept[NPG];
    __shared__ int   nid[NPG];
    __shared__ int   inv[KNUM];
    __shared__ float scl[KNUM];
    __shared__ int   rpA[NPG];
    __shared__ int   rpB[NPG];
    __shared__ unsigned wbal[4];

    const unsigned FULL = 0xffffffffu;
    const int b     = blockIdx.x;
    const int t     = threadIdx.x;
    const int warp  = t >> 5, lane = t & 31;
    const int base  = b * NPG;
    const int ebase = b * EPG;

    if (t < F_DIM) th[t] = theta[t];
    if (t < NPG)   z[t] = 0.0f;
    for (int i = t; i < NWARP * NPG; i += TPB) ((int*)degp)[i] = 0;
    __syncthreads();

    // ---- s[i] = dot(x[base+i,:], theta) : one warp per node ----
    {
        float4 tv = reinterpret_cast<const float4*>(th)[lane];
        for (int i = warp; i < NPG; i += NWARP) {
            float4 v = reinterpret_cast<const float4*>(x + (size_t)(base + i) * F_DIM)[lane];
            float d = v.x * tv.x + v.y * tv.y + v.z * tv.z + v.w * tv.w;
            #pragma unroll
            for (int o = 16; o > 0; o >>= 1) d += __shfl_down_sync(FULL, d, o);
            if (lane == 0) s[i] = d;
        }
    }

    // ---- int4 edge load -> smem local ids + atomic-free degree histogram ----
    {
        const int4* src4 = reinterpret_cast<const int4*>(ei + ebase);
        const int4* dst4 = reinterpret_cast<const int4*>(ei + (size_t)E + ebase);
        for (int q0 = 0; q0 < EPG / 4; q0 += TPB) {
            int q = q0 + t;
            unsigned act = __ballot_sync(FULL, q < EPG / 4);
            if (q < EPG / 4) {
                int4 sv = src4[q]; int4 dv = dst4[q];
                sv.x -= base; sv.y -= base; sv.z -= base; sv.w -= base;
                dv.x -= base; dv.y -= base; dv.z -= base; dv.w -= base;
                reinterpret_cast<int4*>(srcl)[q] = sv;
                reinterpret_cast<int4*>(dstl)[q] = dv;
                int vals[4] = {sv.x, sv.y, sv.z, sv.w};
                #pragma unroll
                for (int c = 0; c < 4; c++) {
                    unsigned grp = __match_any_sync(act, vals[c]);
                    if ((grp & ((1u << lane) - 1u)) == 0)  // lowest-lane leader
                        degp[warp][vals[c]] += __popc(grp);
                }
            }
        }
    }
    __syncthreads();

    // ---- per-node: deg, dis, us, self-loop term ----
    if (t < NPG) {
        int d = 1;
        #pragma unroll
        for (int w = 0; w < NWARP; w++) d += degp[w][t];
        float fd = (float)d;
        float r  = rsqrtf(fd);
        float sv = s[t];
        dis[t] = r;
        us[t]  = r * sv;
        s[t]   = sv / fd;                 // self-loop contribution
    }
    __syncthreads();

    // ---- z[dst] += dis[src]*s[src]  (dis[dst] factored out) ----
    for (int q = t; q < EPG / 4; q += TPB) {
        int4 sv = reinterpret_cast<const int4*>(srcl)[q];
        int4 dv = reinterpret_cast<const int4*>(dstl)[q];
        atomicAdd(&z[dv.x], us[sv.x]);
        atomicAdd(&z[dv.y], us[sv.y]);
        atomicAdd(&z[dv.z], us[sv.z]);
        atomicAdd(&z[dv.w], us[sv.w]);
    }
    __syncthreads();

    if (t < NPG) z[t] = s[t] + dis[t] * z[t];   // final score
    __syncthreads();

    // ---- rank counting split across all warps (j-halves) ----
    if (t < NPG) {                       // node t, j in [0,50)
        float zi = z[t]; int r = 0;
        #pragma unroll 5
        for (int j = 0; j < NPG / 2; j++) {
            float zj = z[j];
            r += (zj > zi) || (zj == zi && j < t);
        }
        rpA[t] = r;
    } else if (t >= 128 && t < 128 + NPG) {  // node t-128, j in [50,100)
        int i = t - 128;
        float zi = z[i]; int r = 0;
        #pragma unroll 5
        for (int j = NPG / 2; j < NPG; j++) {
            float zj = z[j];
            r += (zj > zi) || (zj == zi && j < i);
        }
        rpB[i] = r;
    }
    __syncthreads();

    // ---- kept flags + per-warp ballots ----
    if (t < 128) {
        int k = (t < NPG) ? ((rpA[t] + rpB[t]) < KNUM) : 0;
        if (t < NPG) kept[t] = k;
        unsigned bal = __ballot_sync(FULL, k);
        if (lane == 0) wbal[warp] = bal;
    }
    __syncthreads();

    // ---- ballot prefix scan -> new ids, inverse map, scales ----
    if (t < NPG && kept[t]) {
        int off = __popc(wbal[warp] & ((1u << lane) - 1u));
        #pragma unroll
        for (int w = 0; w < 4; w++) if (w < warp) off += __popc(wbal[w]);
        nid[t]   = off;
        inv[off] = t;
        scl[off] = 1.0f / (1.0f + __expf(-z[t]));
    }
    __syncthreads();

    // ---- outputs: [x_new | edge0 | edge1 | batch] ----
    const size_t EOUT0 = (size_t)B * KNUM * F_DIM;
    const size_t EOUT1 = EOUT0 + (size_t)E;
    const size_t BOUT  = EOUT0 + 2 * (size_t)E;
    const int bK = b * KNUM;

    // x_new: warp per kept row, float4
    for (int r = warp; r < KNUM; r += NWARP) {
        int i = inv[r];
        float sc = scl[r];
        float4 v = reinterpret_cast<const float4*>(x + (size_t)(base + i) * F_DIM)[lane];
        v.x *= sc; v.y *= sc; v.z *= sc; v.w *= sc;
        reinterpret_cast<float4*>(out + (size_t)(bK + r) * F_DIM)[lane] = v;
    }

    if (t < KNUM) out[BOUT + (size_t)bK + t] = (float)b;

    // relabeled edges, float4 stores
    float4* e0out = reinterpret_cast<float4*>(out + EOUT0 + ebase);
    float4* e1out = reinterpret_cast<float4*>(out + EOUT1 + ebase);
    for (int q = t; q < EPG / 4; q += TPB) {
        int4 sv = reinterpret_cast<const int4*>(srcl)[q];
        int4 dv = reinterpret_cast<const int4*>(dstl)[q];
        float4 o0, o1;
        bool kx = kept[sv.x] && kept[dv.x];
        bool ky = kept[sv.y] && kept[dv.y];
        bool kz = kept[sv.z] && kept[dv.z];
        bool kw = kept[sv.w] && kept[dv.w];
        o0.x = kx ? (float)(bK + nid[sv.x]) : -1.0f;
        o1.x = kx ? (float)(bK + nid[dv.x]) : -1.0f;
        o0.y = ky ? (float)(bK + nid[sv.y]) : -1.0f;
        o1.y = ky ? (float)(bK + nid[dv.y]) : -1.0f;
        o0.z = kz ? (float)(bK + nid[sv.z]) : -1.0f;
        o1.z = kz ? (float)(bK + nid[dv.z]) : -1.0f;
        o0.w = kw ? (float)(bK + nid[sv.w]) : -1.0f;
        o1.w = kw ? (float)(bK + nid[dv.w]) : -1.0f;
        e0out[q] = o0;
        e1out[q] = o1;
    }
}

extern "C" void kernel_launch(void* const* d_in, const int* in_sizes, int n_in,
                              void* d_out, int out_size)
{
    const float* x     = (const float*)d_in[0];
    const int*   ei    = (const int*)d_in[1];
    const float* theta = (const float*)d_in[3];
    float* out = (float*)d_out;

    int N = in_sizes[0] / F_DIM;   // 100000
    int E = in_sizes[1] / 2;       // 1600000
    int B = N / NPG;               // 1000

    sagpool_fused_kernel<<<B, TPB>>>(x, ei, theta, out, E, B);
}

// round 5
// speedup vs baseline: 1.2889x; 1.0513x over previous
#include <cuda_runtime.h>
#include <math.h>

#define F_DIM 128
#define NPG   100
#define KNUM  80
#define EPG   1600
#define TPB   256

__global__ __launch_bounds__(TPB) void sagpool_fused_kernel(
    const float* __restrict__ x,
    const int*   __restrict__ ei,      // [2, E]: [0..E) = src, [E..2E) = dst
    const float* __restrict__ theta,   // [F]
    float* __restrict__ out,
    int E, int B)
{
    __shared__ float s[NPG];           // dot(x_i, theta); later self-loop term s_i/deg_i
    __shared__ float us[NPG];          // dis_i * s_i
    __shared__ float z[NPG];           // scatter accumulator -> final score
    __shared__ float dis[NPG];
    __shared__ int   degp[4][NPG];     // per-warp (warps 4..7) private degree hists
    __shared__ __align__(16) int srcl[EPG];
    __shared__ __align__(16) int dstl[EPG];
    __shared__ float codef[NPG];       // kept ? (float)(b*KNUM+newid) : -1
    __shared__ int   inv[KNUM];
    __shared__ float scl[KNUM];
    __shared__ int   rpA[NPG];
    __shared__ int   rpB[NPG];
    __shared__ unsigned wbal[4];

    const unsigned FULL = 0xffffffffu;
    const int b     = blockIdx.x;
    const int t     = threadIdx.x;
    const int warp  = t >> 5, lane = t & 31;
    const int base  = b * NPG;
    const int ebase = b * EPG;
    const int bK    = b * KNUM;

    // ================= Phase A: warp-specialized =================
    if (warp < 4) {
        // ---- warps 0-3: 100 dot products, 4 rows in flight ----
        // theta loaded straight from global (512B, L2-broadcast, no smem race)
        float4 tv = reinterpret_cast<const float4*>(theta)[lane];

        // rows: i = warp + 4*g, g = 0..24 (25 rows/warp)
        #pragma unroll
        for (int gb = 0; gb < 24; gb += 4) {
            float d[4];
            #pragma unroll
            for (int c = 0; c < 4; c++) {
                int i = warp + 4 * (gb + c);
                float4 v = reinterpret_cast<const float4*>(x + (size_t)(base + i) * F_DIM)[lane];
                d[c] = v.x * tv.x + v.y * tv.y + v.z * tv.z + v.w * tv.w;
            }
            #pragma unroll
            for (int o = 16; o > 0; o >>= 1) {
                #pragma unroll
                for (int c = 0; c < 4; c++) d[c] += __shfl_down_sync(FULL, d[c], o);
            }
            if (lane == 0) {
                #pragma unroll
                for (int c = 0; c < 4; c++) s[warp + 4 * (gb + c)] = d[c];
            }
        }
        {   // leftover row g = 24
            int i = warp + 96;
            float4 v = reinterpret_cast<const float4*>(x + (size_t)(base + i) * F_DIM)[lane];
            float d = v.x * tv.x + v.y * tv.y + v.z * tv.z + v.w * tv.w;
            #pragma unroll
            for (int o = 16; o > 0; o >>= 1) d += __shfl_down_sync(FULL, d, o);
            if (lane == 0) s[i] = d;
        }
    } else {
        // ---- warps 4-7: init z + private hist, load edges, degree histogram ----
        const int w  = warp - 4;
        const int tt = t - 128;            // 0..127
        for (int i = lane; i < NPG; i += 32) {
            degp[w][i] = 0;
            if (w == 0) z[i] = 0.0f;
        }
        __syncwarp();

        const int4* src4 = reinterpret_cast<const int4*>(ei + ebase);
        const int4* dst4 = reinterpret_cast<const int4*>(ei + (size_t)E + ebase);
        for (int q0 = 0; q0 < EPG / 4; q0 += 128) {
            int q = q0 + tt;
            unsigned act = __ballot_sync(FULL, q < EPG / 4);
            if (q < EPG / 4) {
                int4 sv = src4[q]; int4 dv = dst4[q];
                sv.x -= base; sv.y -= base; sv.z -= base; sv.w -= base;
                dv.x -= base; dv.y -= base; dv.z -= base; dv.w -= base;
                reinterpret_cast<int4*>(srcl)[q] = sv;
                reinterpret_cast<int4*>(dstl)[q] = dv;
                int vals[4] = {sv.x, sv.y, sv.z, sv.w};
                #pragma unroll
                for (int c = 0; c < 4; c++) {
                    unsigned grp = __match_any_sync(act, vals[c]);
                    if ((grp & ((1u << lane) - 1u)) == 0)
                        degp[w][vals[c]] += __popc(grp);
                }
            }
        }
    }
    __syncthreads();

    // ================= per-node: deg, dis, us, self term =================
    if (t < NPG) {
        int d = 1 + degp[0][t] + degp[1][t] + degp[2][t] + degp[3][t];
        float fd = (float)d;
        float r  = rsqrtf(fd);
        float sv = s[t];
        dis[t] = r;
        us[t]  = r * sv;
        s[t]   = sv / fd;
    }
    __syncthreads();

    // ================= z[dst] += dis[src]*s[src] =================
    for (int q = t; q < EPG / 4; q += TPB) {
        int4 sv = reinterpret_cast<const int4*>(srcl)[q];
        int4 dv = reinterpret_cast<const int4*>(dstl)[q];
        atomicAdd(&z[dv.x], us[sv.x]);
        atomicAdd(&z[dv.y], us[sv.y]);
        atomicAdd(&z[dv.z], us[sv.z]);
        atomicAdd(&z[dv.w], us[sv.w]);
    }
    __syncthreads();

    if (t < NPG) z[t] = s[t] + dis[t] * z[t];
    __syncthreads();

    // ================= rank counting, split j-halves across warp groups =================
    if (t < NPG) {
        float zi = z[t]; int r = 0;
        #pragma unroll 5
        for (int j = 0; j < NPG / 2; j++) {
            float zj = z[j];
            r += (zj > zi) || (zj == zi && j < t);
        }
        rpA[t] = r;
    } else if (t >= 128 && t < 128 + NPG) {
        int i = t - 128;
        float zi = z[i]; int r = 0;
        #pragma unroll 5
        for (int j = NPG / 2; j < NPG; j++) {
            float zj = z[j];
            r += (zj > zi) || (zj == zi && j < i);
        }
        rpB[i] = r;
    }
    __syncthreads();

    // ================= kept (in registers) + ballots =================
    int k = 0;
    if (t < 128) {
        k = (t < NPG) ? ((rpA[t] + rpB[t]) < KNUM) : 0;
        unsigned bal = __ballot_sync(FULL, k);
        if (lane == 0) wbal[warp] = bal;
    }
    __syncthreads();

    // ================= scan -> codef, inv, scl =================
    if (t < NPG) {
        int off = __popc(wbal[warp] & ((1u << lane) - 1u));
        #pragma unroll
        for (int w = 0; w < 4; w++) if (w < warp) off += __popc(wbal[w]);
        codef[t] = k ? (float)(bK + off) : -1.0f;
        if (k) {
            inv[off] = t;
            scl[off] = 1.0f / (1.0f + __expf(-z[t]));
        }
    }
    __syncthreads();

    // ================= outputs: [x_new | edge0 | edge1 | batch] =================
    const size_t EOUT0 = (size_t)B * KNUM * F_DIM;
    const size_t EOUT1 = EOUT0 + (size_t)E;
    const size_t BOUT  = EOUT0 + 2 * (size_t)E;

    // x_new: warp per kept row (10 rows/warp), float4
    for (int r = warp; r < KNUM; r += 8) {
        int i = inv[r];
        float sc = scl[r];
        float4 v = reinterpret_cast<const float4*>(x + (size_t)(base + i) * F_DIM)[lane];
        v.x *= sc; v.y *= sc; v.z *= sc; v.w *= sc;
        reinterpret_cast<float4*>(out + (size_t)(bK + r) * F_DIM)[lane] = v;
    }

    if (t < KNUM) out[BOUT + (size_t)bK + t] = (float)b;

    // relabeled edges via codef: 2 LDS + 2 selects per edge
    float4* e0out = reinterpret_cast<float4*>(out + EOUT0 + ebase);
    float4* e1out = reinterpret_cast<float4*>(out + EOUT1 + ebase);
    for (int q = t; q < EPG / 4; q += TPB) {
        int4 sv = reinterpret_cast<const int4*>(srcl)[q];
        int4 dv = reinterpret_cast<const int4*>(dstl)[q];
        float4 o0, o1;
        float cs, cd;
        cs = codef[sv.x]; cd = codef[dv.x];
        o0.x = (cd < 0.0f) ? -1.0f : cs;  o1.x = (cs < 0.0f) ? -1.0f : cd;
        cs = codef[sv.y]; cd = codef[dv.y];
        o0.y = (cd < 0.0f) ? -1.0f : cs;  o1.y = (cs < 0.0f) ? -1.0f : cd;
        cs = codef[sv.z]; cd = codef[dv.z];
        o0.z = (cd < 0.0f) ? -1.0f : cs;  o1.z = (cs < 0.0f) ? -1.0f : cd;
        cs = codef[sv.w]; cd = codef[dv.w];
        o0.w = (cd < 0.0f) ? -1.0f : cs;  o1.w = (cs < 0.0f) ? -1.0f : cd;
        e0out[q] = o0;
        e1out[q] = o1;
    }
}

extern "C" void kernel_launch(void* const* d_in, const int* in_sizes, int n_in,
                              void* d_out, int out_size)
{
    const float* x     = (const float*)d_in[0];
    const int*   ei    = (const int*)d_in[1];
    const float* theta = (const float*)d_in[3];
    float* out = (float*)d_out;

    int N = in_sizes[0] / F_DIM;   // 100000
    int E = in_sizes[1] / 2;       // 1600000
    int B = N / NPG;               // 1000

    sagpool_fused_kernel<<<B, TPB>>>(x, ei, theta, out, E, B);
}